// round 3
// baseline (speedup 1.0000x reference)
#include <cuda_runtime.h>
#include <cmath>

// Problem shapes (fixed per reference)
#define B_   32
#define S_   4096
#define QD   512
#define KVD  512

#define NC       32            // chunks per batch for kernel2
#define ROWS_    (S_ / NC)     // 128 rows per chunk
#define QSLICES  8             // q-slices for kernel1
#define QS_LEN   (QD / QSLICES) // 64

// Scratch (device globals; no allocation allowed)
__device__ float g_wqp[QSLICES * B_ * KVD];     // partial W^T q  (512 KB)
__device__ float g_pm[B_ * NC];
__device__ float g_pl[B_ * NC];
__device__ float g_pacc[B_ * NC * KVD];         // 2 MB

// ---------------------------------------------------------------------------
// Kernel 1: partial wq[b,k] over a q-slice.  grid(QSLICES, B), 512 threads.
// wqp[qs][b][k] = sum_{q in slice} W[q][k] * query[b][q]
// ---------------------------------------------------------------------------
__global__ void __launch_bounds__(512) k1_wq(const float* __restrict__ query,
                                             const float* __restrict__ weight) {
    const int qs = blockIdx.x;
    const int b  = blockIdx.y;
    const int k  = threadIdx.x;   // 0..511

    __shared__ float sq[QS_LEN];
    if (k < QS_LEN) sq[k] = query[b * QD + qs * QS_LEN + k];
    __syncthreads();

    const float* Wp = weight + (size_t)(qs * QS_LEN) * KVD + k;
    float s = 0.f;
#pragma unroll 16
    for (int q = 0; q < QS_LEN; ++q)
        s += sq[q] * Wp[(size_t)q * KVD];

    g_wqp[((size_t)qs * B_ + b) * KVD + k] = s;
}

// ---------------------------------------------------------------------------
// Kernel 2: fused masked-score + online softmax + weighted sum over a chunk.
// grid(NC, B), 256 threads (8 warps).  Warp-per-row; lane owns 16 k-values.
// ---------------------------------------------------------------------------
__global__ void __launch_bounds__(256, 3) k2_fused(const float* __restrict__ kv,
                                                   const int*   __restrict__ mask) {
    const int c   = blockIdx.x;    // chunk
    const int b   = blockIdx.y;    // batch
    const int tid = threadIdx.x;
    const int w   = tid >> 5;      // warp 0..7
    const int lane = tid & 31;

    __shared__ float s_m[8];
    __shared__ float s_l[8];
    __shared__ float s_acc[8][KVD];   // 16 KB; first row doubles as wq staging

    // --- stage wq = sum of q-slice partials into shared, then into regs ---
    float* swq = &s_acc[0][0];
    for (int i = tid; i < KVD; i += 256) {
        float s = 0.f;
#pragma unroll
        for (int j = 0; j < QSLICES; ++j)
            s += g_wqp[((size_t)j * B_ + b) * KVD + i];
        swq[i] = s;
    }
    __syncthreads();

    float4 wqr[4];
    const float4* swq4 = (const float4*)swq;
#pragma unroll
    for (int j = 0; j < 4; ++j) wqr[j] = swq4[j * 32 + lane];
    __syncthreads();   // done reading swq; s_acc reusable after the loop

    // --- stream rows: online softmax + accumulation ---
    const size_t rowbase = ((size_t)b * S_ + (size_t)c * ROWS_);
    const float4* kv4 = (const float4*)(kv + rowbase * KVD);
    const int*    mb  = mask + rowbase;

    float m = -1e30f, l = 0.f;
    float4 acc[4];
#pragma unroll
    for (int j = 0; j < 4; ++j) acc[j] = make_float4(0.f, 0.f, 0.f, 0.f);

    const int ITERS = ROWS_ / 8;  // 16 rows per warp

    // prologue: load row r0 = w
    float4 cur[4], nxt[4];
    {
        const float4* rp = kv4 + (size_t)w * (KVD / 4);
#pragma unroll
        for (int j = 0; j < 4; ++j) cur[j] = rp[j * 32 + lane];
    }
    int curmask = mb[w];
    int nxtmask = 0;

    for (int it = 0; it < ITERS; ++it) {
        // prefetch next row (uniform branch)
        if (it + 1 < ITERS) {
            const int rn = w + 8 * (it + 1);
            const float4* rp = kv4 + (size_t)rn * (KVD / 4);
#pragma unroll
            for (int j = 0; j < 4; ++j) nxt[j] = rp[j * 32 + lane];
            nxtmask = mb[rn];
        }

        // dot(kv_row, wq)
        float d = 0.f;
#pragma unroll
        for (int j = 0; j < 4; ++j) {
            d += cur[j].x * wqr[j].x;
            d += cur[j].y * wqr[j].y;
            d += cur[j].z * wqr[j].z;
            d += cur[j].w * wqr[j].w;
        }
#pragma unroll
        for (int off = 16; off > 0; off >>= 1)
            d += __shfl_xor_sync(0xFFFFFFFFu, d, off);

        const bool valid = (curmask != 0);
        const float dv   = valid ? d : -1e30f;
        const float mnew = fmaxf(m, dv);
        const float alpha = __expf(m - mnew);          // ==1 when m unchanged
        const float p     = valid ? __expf(d - mnew) : 0.f;

        l = l * alpha + p;
#pragma unroll
        for (int j = 0; j < 4; ++j) {
            acc[j].x = acc[j].x * alpha + p * cur[j].x;
            acc[j].y = acc[j].y * alpha + p * cur[j].y;
            acc[j].z = acc[j].z * alpha + p * cur[j].z;
            acc[j].w = acc[j].w * alpha + p * cur[j].w;
        }
        m = mnew;

#pragma unroll
        for (int j = 0; j < 4; ++j) cur[j] = nxt[j];
        curmask = nxtmask;
    }

    // --- block combine across 8 warps ---
    if (lane == 0) { s_m[w] = m; s_l[w] = l; }
    float4* srow = (float4*)s_acc[w];
#pragma unroll
    for (int j = 0; j < 4; ++j) srow[j * 32 + lane] = acc[j];
    __syncthreads();

    float mblk = -1e30f;
#pragma unroll
    for (int w2 = 0; w2 < 8; ++w2) mblk = fmaxf(mblk, s_m[w2]);
    float f[8];
    float lblk = 0.f;
#pragma unroll
    for (int w2 = 0; w2 < 8; ++w2) {
        f[w2] = __expf(s_m[w2] - mblk);
        lblk += f[w2] * s_l[w2];
    }

    const size_t pbase = ((size_t)b * NC + c) * KVD;
    for (int k = tid; k < KVD; k += 256) {
        float v = 0.f;
#pragma unroll
        for (int w2 = 0; w2 < 8; ++w2) v += f[w2] * s_acc[w2][k];
        g_pacc[pbase + k] = v;
    }
    if (tid == 0) { g_pm[b * NC + c] = mblk; g_pl[b * NC + c] = lblk; }
}

// ---------------------------------------------------------------------------
// Kernel 3: combine chunk partials.  grid(B), 256 threads (k and k+256).
// ---------------------------------------------------------------------------
__global__ void __launch_bounds__(256) k3_combine(float* __restrict__ out) {
    const int b   = blockIdx.x;
    const int tid = threadIdx.x;

    __shared__ float spm[NC], spl[NC];
    if (tid < NC) { spm[tid] = g_pm[b * NC + tid]; spl[tid] = g_pl[b * NC + tid]; }
    __syncthreads();

    float mstar = -1e30f;
#pragma unroll
    for (int cc = 0; cc < NC; ++cc) mstar = fmaxf(mstar, spm[cc]);

    float denom = 0.f, n0 = 0.f, n1 = 0.f;
#pragma unroll 4
    for (int cc = 0; cc < NC; ++cc) {
        const float fc = __expf(spm[cc] - mstar);
        denom += fc * spl[cc];
        const size_t pbase = ((size_t)b * NC + cc) * KVD;
        n0 += fc * g_pacc[pbase + tid];
        n1 += fc * g_pacc[pbase + tid + 256];
    }
    out[b * KVD + tid]       = n0 / denom;
    out[b * KVD + tid + 256] = n1 / denom;
}

// ---------------------------------------------------------------------------
extern "C" void kernel_launch(void* const* d_in, const int* in_sizes, int n_in,
                              void* d_out, int out_size) {
    const float* query  = (const float*)d_in[0];   // [32, 512]
    const float* kv     = (const float*)d_in[1];   // [32, 4096, 512]
    const int*   mask   = (const int*)  d_in[2];   // [32, 4096]
    const float* weight = (const float*)d_in[3];   // [512, 512]
    float* out = (float*)d_out;                    // [32, 512]

    (void)in_sizes; (void)n_in; (void)out_size;

    k1_wq<<<dim3(QSLICES, B_), 512>>>(query, weight);
    k2_fused<<<dim3(NC, B_), 256>>>(kv, mask);
    k3_combine<<<B_, 256>>>(out);
}